// round 2
// baseline (speedup 1.0000x reference)
#include <cuda_runtime.h>
#include <cuda_bf16.h>
#include <cstdint>

#define T_LEN 2048
#define EMB   256
#define H2    256
#define G4    1024
#define C_TAGS 12
#define NEGV  (-10000.0f)
#define START_TAG 10
#define STOP_TAG  11

// ---------------------------------------------------------------- scratch
__device__ float g_pre[2][T_LEN][G4];    // 16 MB: gate pre-activations
__device__ float g_hs[2][T_LEN][H2];     // 4 MB: hidden states per direction
__device__ float g_feats[T_LEN][C_TAGS]; // 96 KB

__device__ __forceinline__ uint32_t smem_u32(const void* p) {
    return (uint32_t)__cvta_generic_to_shared(p);
}

__device__ __forceinline__ float sigf(float x) {
    return 1.0f / (1.0f + expf(-x));
}

// ============================================================ Phase 1: GEMM
// g_pre[dir][t][r] = sum_k Wih[r][k] * emb[sent[t]][k] + bih[r] + bhh[r]
__global__ void gates_gemm(const int* __restrict__ sent,
                           const float* __restrict__ emb,
                           const float* __restrict__ Wih_f,
                           const float* __restrict__ bih_f,
                           const float* __restrict__ bhh_f,
                           const float* __restrict__ Wih_b,
                           const float* __restrict__ bih_b,
                           const float* __restrict__ bhh_b)
{
    const int dir = blockIdx.z;
    const float* Wih = dir ? Wih_b : Wih_f;
    const float* bih = dir ? bih_b : bih_f;
    const float* bhh = dir ? bhh_b : bhh_f;
    const int t0 = blockIdx.x * 32;
    const int r0 = blockIdx.y * 32;
    const int tid = threadIdx.x;
    const int lane = tid & 31;
    const int warp = tid >> 5;

    __shared__ float Xs[32][33];
    __shared__ float Ws[32][33];
    __shared__ int   sidx[32];

    if (tid < 32) sidx[tid] = sent[t0 + tid];
    __syncthreads();

    float acc[4] = {0.f, 0.f, 0.f, 0.f};
    for (int kc = 0; kc < EMB; kc += 32) {
        #pragma unroll
        for (int e = 0; e < 4; e++) {
            int idx = tid + 256 * e;
            int a = idx >> 5, b = idx & 31;
            Xs[a][b] = emb[(long long)sidx[a] * EMB + kc + b];
            Ws[a][b] = Wih[(r0 + a) * EMB + kc + b];
        }
        __syncthreads();
        #pragma unroll
        for (int k = 0; k < 32; k++) {
            float wk = Ws[lane][k];
            #pragma unroll
            for (int e = 0; e < 4; e++)
                acc[e] += Xs[warp + 8 * e][k] * wk;
        }
        __syncthreads();
    }
    float bias = bih[r0 + lane] + bhh[r0 + lane];
    #pragma unroll
    for (int e = 0; e < 4; e++)
        g_pre[dir][t0 + warp + 8 * e][r0 + lane] = acc[e] + bias;
}

// ====================================================== Phase 2: recurrence
// 2 clusters of 8 CTAs (one per direction). CTA `rank` owns h indices
// [32*rank, 32*rank+32) and gate rows {g*256 + 32*rank + j : g<4, j<32}.
// Whh rows live in registers (64 floats / thread).
__global__ void __cluster_dims__(8, 1, 1) __launch_bounds__(512, 1)
lstm_rec(const float* __restrict__ Whh_f,
         const float* __restrict__ Whh_b,
         const float* __restrict__ h0,
         const float* __restrict__ c0)
{
    const int dir  = blockIdx.x >> 3;
    unsigned rank;
    asm("mov.u32 %0, %%cluster_ctarank;" : "=r"(rank));
    const float* Whh = dir ? Whh_b : Whh_f;

    const int tid = threadIdx.x;
    const int lr  = tid >> 2;     // local gate row 0..127
    const int seg = tid & 3;      // 64-col segment
    const int gg  = lr >> 5;      // gate id 0..3 (i,f,g,o)
    const int jj  = lr & 31;      // h index within CTA
    const int grow = (gg << 8) + (int)(rank << 5) + jj;  // global gate row

    __shared__ float    hbuf[2][H2];
    __shared__ float    gates[128];
    __shared__ uint64_t bars[2];

    // weights -> registers
    float w[64];
    const float* wrow = Whh + grow * H2 + seg * 64;
    #pragma unroll
    for (int i = 0; i < 16; i++) {
        float4 v = *(const float4*)(wrow + 4 * i);
        w[4*i] = v.x; w[4*i+1] = v.y; w[4*i+2] = v.z; w[4*i+3] = v.w;
    }

    // init h, c, barriers
    if (tid < H2) hbuf[0][tid] = h0[dir * H2 + tid];
    float creg = 0.f;
    if (tid < 32) creg = c0[dir * H2 + (int)rank * 32 + tid];
    if (tid == 0) {
        uint32_t b0 = smem_u32(&bars[0]);
        uint32_t b1 = smem_u32(&bars[1]);
        asm volatile("mbarrier.init.shared.b64 [%0], %1;" :: "r"(b0), "r"(256) : "memory");
        asm volatile("mbarrier.init.shared.b64 [%0], %1;" :: "r"(b1), "r"(256) : "memory");
    }
    __syncthreads();
    asm volatile("barrier.cluster.arrive.aligned;" ::: "memory");
    asm volatile("barrier.cluster.wait.aligned;"  ::: "memory");

    int ph0 = 0, ph1 = 0;
    const uint32_t bar0 = smem_u32(&bars[0]);
    const uint32_t bar1 = smem_u32(&bars[1]);

    for (int it = 0; it < T_LEN; it++) {
        const int buf = it & 1;
        const int t = dir ? (T_LEN - 1 - it) : it;

        if (it > 0) {
            uint32_t ba = buf ? bar1 : bar0;
            int      ph = buf ? ph1  : ph0;
            asm volatile(
                "{\n\t.reg .pred P;\n\t"
                "BW_%=:\n\t"
                "mbarrier.try_wait.parity.acquire.cluster.shared::cta.b64 P, [%0], %1, 0x989680;\n\t"
                "@P bra.uni BWD_%=;\n\t"
                "bra.uni BW_%=;\n\t"
                "BWD_%=:\n\t}"
                :: "r"(ba), "r"(ph) : "memory");
            if (buf) ph1 ^= 1; else ph0 ^= 1;
        }

        // prefetch pre-activation (leaders only)
        float gp = 0.f;
        if (seg == 0) gp = g_pre[dir][t][grow];

        // h . w  (64-element segment)
        const float* hp = hbuf[buf] + seg * 64;
        float acc = 0.f;
        #pragma unroll
        for (int i = 0; i < 16; i++) {
            float4 hv = *(const float4*)(hp + 4 * i);
            acc += w[4*i] * hv.x + w[4*i+1] * hv.y + w[4*i+2] * hv.z + w[4*i+3] * hv.w;
        }
        acc += __shfl_down_sync(0xffffffffu, acc, 2, 4);
        acc += __shfl_down_sync(0xffffffffu, acc, 1, 4);
        if (seg == 0) gates[lr] = acc + gp;
        __syncthreads();

        if (tid < 32) {
            float iv = gates[tid];
            float fv = gates[32 + tid];
            float gv = gates[64 + tid];
            float ov = gates[96 + tid];
            creg = sigf(fv) * creg + sigf(iv) * tanhf(gv);
            float h = sigf(ov) * tanhf(creg);

            const int hidx = (int)rank * 32 + tid;
            g_hs[dir][t][hidx] = h;

            if (it < T_LEN - 1) {
                const int nbuf = buf ^ 1;
                uint32_t loc    = smem_u32(&hbuf[nbuf][hidx]);
                uint32_t barloc = nbuf ? bar1 : bar0;
                #pragma unroll
                for (int r = 0; r < 8; r++) {
                    asm volatile(
                        "{\n\t.reg .b32 ra;\n\t"
                        "mapa.shared::cluster.u32 ra, %0, %1;\n\t"
                        "st.shared::cluster.f32 [ra], %2;\n\t}"
                        :: "r"(loc), "r"(r), "f"(h) : "memory");
                }
                #pragma unroll
                for (int r = 0; r < 8; r++) {
                    asm volatile(
                        "{\n\t.reg .b32 ra;\n\t"
                        "mapa.shared::cluster.u32 ra, %0, %1;\n\t"
                        "mbarrier.arrive.release.cluster.shared::cluster.b64 _, [ra];\n\t}"
                        :: "r"(barloc), "r"(r) : "memory");
                }
            }
        }
    }
}

// ========================================================= Phase 3: feats
// feats[t][c] = [hf[t], hb[t]] . Wlin[c] + blin[c]; one warp per t.
__global__ void feats_kernel(const float* __restrict__ Wlin,
                             const float* __restrict__ blin)
{
    __shared__ float Wl[C_TAGS][512];
    const int tid = threadIdx.x;
    for (int i = tid; i < C_TAGS * 512; i += 256)
        Wl[i >> 9][i & 511] = Wlin[i];
    __syncthreads();

    const int warp = tid >> 5, lane = tid & 31;
    const int t = blockIdx.x * 8 + warp;

    float hv[16];
    #pragma unroll
    for (int i = 0; i < 8; i++) hv[i]     = g_hs[0][t][lane + 32 * i];
    #pragma unroll
    for (int i = 0; i < 8; i++) hv[8 + i] = g_hs[1][t][lane + 32 * i];

    #pragma unroll
    for (int c = 0; c < C_TAGS; c++) {
        float a = 0.f;
        #pragma unroll
        for (int i = 0; i < 16; i++)
            a += hv[i] * Wl[c][lane + 32 * i];
        #pragma unroll
        for (int o = 16; o; o >>= 1)
            a += __shfl_down_sync(0xffffffffu, a, o);
        if (lane == 0) g_feats[t][c] = a + blin[c];
    }
}

// ================================================ Phase 4: Viterbi + trace
__global__ void viterbi_kernel(const float* __restrict__ trans,
                               float* __restrict__ out, int out_size)
{
    __shared__ uint8_t bps[T_LEN][C_TAGS];   // 24 KB
    __shared__ float   fvs[16];

    const int lane = threadIdx.x;
    float tr[C_TAGS];
    if (lane < C_TAGS) {
        #pragma unroll
        for (int p = 0; p < C_TAGS; p++) tr[p] = trans[lane * C_TAGS + p];
    }
    float fv = (lane == START_TAG) ? 0.f : NEGV;

    auto featload = [&](int idx) -> float {
        return (lane < C_TAGS && idx < T_LEN) ? g_feats[idx][lane] : 0.f;
    };
    auto vstep = [&](int t, float ft) {
        if (lane < C_TAGS) fvs[lane] = fv;
        __syncwarp();
        if (lane < C_TAGS) {
            float best = -3.4e38f; int bp = 0;
            #pragma unroll
            for (int p = 0; p < C_TAGS; p++) {
                float s = fvs[p] + tr[p];
                if (s > best) { best = s; bp = p; }
            }
            fv = best + ft;
            bps[t][lane] = (uint8_t)bp;
        }
        __syncwarp();
    };

    float f0 = featload(0), f1 = featload(1), f2 = featload(2), f3 = featload(3);
    for (int t = 0; t < T_LEN; t += 4) {
        float n0 = featload(t + 4), n1 = featload(t + 5);
        float n2 = featload(t + 6), n3 = featload(t + 7);
        vstep(t + 0, f0);
        vstep(t + 1, f1);
        vstep(t + 2, f2);
        vstep(t + 3, f3);
        f0 = n0; f1 = n1; f2 = n2; f3 = n3;
    }

    if (lane < C_TAGS) fvs[lane] = fv + trans[STOP_TAG * C_TAGS + lane];
    __syncwarp();

    if (lane == 0) {
        float best = fvs[0]; int bt = 0;
        #pragma unroll
        for (int p = 1; p < C_TAGS; p++)
            if (fvs[p] > best) { best = fvs[p]; bt = p; }

        if (out_size >= 1) out[0] = best;
        if (out_size >= T_LEN + 1) {
            int tag = bt;
            for (int t = T_LEN - 1; t >= 1; t--) {
                out[1 + t] = (float)tag;
                tag = bps[t][tag];
            }
            out[1] = (float)tag;
        }
    }
}

// ================================================================= launch
extern "C" void kernel_launch(void* const* d_in, const int* in_sizes, int n_in,
                              void* d_out, int out_size)
{
    const int*   sent   = (const int*)  d_in[0];
    const float* emb    = (const float*)d_in[1];
    const float* Wih_f  = (const float*)d_in[2];
    const float* Whh_f  = (const float*)d_in[3];
    const float* bih_f  = (const float*)d_in[4];
    const float* bhh_f  = (const float*)d_in[5];
    const float* Wih_b  = (const float*)d_in[6];
    const float* Whh_b  = (const float*)d_in[7];
    const float* bih_b  = (const float*)d_in[8];
    const float* bhh_b  = (const float*)d_in[9];
    const float* Wlin   = (const float*)d_in[10];
    const float* blin   = (const float*)d_in[11];
    const float* h0     = (const float*)d_in[12];
    const float* c0     = (const float*)d_in[13];
    const float* transi = (const float*)d_in[14];
    float* out = (float*)d_out;

    gates_gemm<<<dim3(T_LEN / 32, G4 / 32, 2), 256>>>(
        sent, emb, Wih_f, bih_f, bhh_f, Wih_b, bih_b, bhh_b);

    lstm_rec<<<16, 512>>>(Whh_f, Whh_b, h0, c0);

    feats_kernel<<<T_LEN / 8, 256>>>(Wlin, blin);

    viterbi_kernel<<<1, 32>>>(transi, out, out_size);
}

// round 3
// speedup vs baseline: 1.5545x; 1.5545x over previous
#include <cuda_runtime.h>
#include <cuda_bf16.h>
#include <cstdint>

#define T_LEN 2048
#define EMB   256
#define H2    256
#define G4    1024
#define C_TAGS 12
#define NEGV  (-10000.0f)
#define START_TAG 10
#define STOP_TAG  11

// ---------------------------------------------------------------- scratch
__device__ float g_pre[2][T_LEN][G4];    // 16 MB: gate pre-activations
__device__ float g_hs[2][T_LEN][H2];     // 4 MB: hidden states per direction
__device__ float g_feats[T_LEN][C_TAGS]; // 96 KB

__device__ __forceinline__ uint32_t smem_u32(const void* p) {
    return (uint32_t)__cvta_generic_to_shared(p);
}

__device__ __forceinline__ float fast_sig(float x) {
    return __fdividef(1.0f, 1.0f + __expf(-x));
}
__device__ __forceinline__ float fast_tanh(float x) {
    return __fdividef(2.0f, 1.0f + __expf(-2.0f * x)) - 1.0f;
}

__device__ __forceinline__ void fma2(uint64_t& d, uint64_t a, uint64_t b) {
    asm("fma.rn.f32x2 %0, %1, %2, %0;" : "+l"(d) : "l"(a), "l"(b));
}
__device__ __forceinline__ float unpack_sum(uint64_t a) {
    float lo, hi;
    asm("mov.b64 {%0, %1}, %2;" : "=f"(lo), "=f"(hi) : "l"(a));
    return lo + hi;
}

// ============================================================ Phase 1: GEMM
__global__ void gates_gemm(const int* __restrict__ sent,
                           const float* __restrict__ emb,
                           const float* __restrict__ Wih_f,
                           const float* __restrict__ bih_f,
                           const float* __restrict__ bhh_f,
                           const float* __restrict__ Wih_b,
                           const float* __restrict__ bih_b,
                           const float* __restrict__ bhh_b)
{
    const int dir = blockIdx.z;
    const float* Wih = dir ? Wih_b : Wih_f;
    const float* bih = dir ? bih_b : bih_f;
    const float* bhh = dir ? bhh_b : bhh_f;
    const int t0 = blockIdx.x * 32;
    const int r0 = blockIdx.y * 32;
    const int tid = threadIdx.x;
    const int lane = tid & 31;
    const int warp = tid >> 5;

    __shared__ float Xs[32][33];
    __shared__ float Ws[32][33];
    __shared__ int   sidx[32];

    if (tid < 32) sidx[tid] = sent[t0 + tid];
    __syncthreads();

    float acc[4] = {0.f, 0.f, 0.f, 0.f};
    for (int kc = 0; kc < EMB; kc += 32) {
        #pragma unroll
        for (int e = 0; e < 4; e++) {
            int idx = tid + 256 * e;
            int a = idx >> 5, b = idx & 31;
            Xs[a][b] = emb[(long long)sidx[a] * EMB + kc + b];
            Ws[a][b] = Wih[(r0 + a) * EMB + kc + b];
        }
        __syncthreads();
        #pragma unroll
        for (int k = 0; k < 32; k++) {
            float wk = Ws[lane][k];
            #pragma unroll
            for (int e = 0; e < 4; e++)
                acc[e] += Xs[warp + 8 * e][k] * wk;
        }
        __syncthreads();
    }
    float bias = bih[r0 + lane] + bhh[r0 + lane];
    #pragma unroll
    for (int e = 0; e < 4; e++)
        g_pre[dir][t0 + warp + 8 * e][r0 + lane] = acc[e] + bias;
}

// ====================================================== Phase 2: recurrence
// 2 clusters of 8 CTAs (one per direction). CTA `rank` owns h indices
// [32*rank, 32*rank+32) and gate rows {g*256 + 32*rank + j}.
// Whh rows in registers as packed f32x2. h broadcast via st.async
// (remote smem store + mbarrier complete_tx; NO cluster-scope fences).
__global__ void __cluster_dims__(8, 1, 1) __launch_bounds__(512, 1)
lstm_rec(const float* __restrict__ Whh_f,
         const float* __restrict__ Whh_b,
         const float* __restrict__ h0,
         const float* __restrict__ c0)
{
    const int dir  = blockIdx.x >> 3;
    unsigned rank;
    asm("mov.u32 %0, %%cluster_ctarank;" : "=r"(rank));
    const float* Whh = dir ? Whh_b : Whh_f;

    const int tid = threadIdx.x;
    const int lr  = tid >> 2;     // local gate row 0..127
    const int seg = tid & 3;      // 64-col segment
    const int gg  = lr >> 5;      // gate id 0..3 (i,f,g,o)
    const int jj  = lr & 31;      // h index within CTA
    const int grow = (gg << 8) + (int)(rank << 5) + jj;

    __shared__ __align__(16) float hbuf[2][H2];
    __shared__ float    gates[128];
    __shared__ uint64_t bars[2];

    // weights -> packed f32x2 registers
    uint64_t w2[32];
    {
        const ulonglong2* wp = (const ulonglong2*)(Whh + grow * H2 + seg * 64);
        #pragma unroll
        for (int i = 0; i < 16; i++) {
            ulonglong2 v = wp[i];
            w2[2*i] = v.x; w2[2*i+1] = v.y;
        }
    }

    // init h, c, barriers
    if (tid < H2) hbuf[0][tid] = h0[dir * H2 + tid];
    float creg = 0.f;
    if (tid < 32) creg = c0[dir * H2 + (int)rank * 32 + tid];

    const uint32_t bar0 = smem_u32(&bars[0]);
    const uint32_t bar1 = smem_u32(&bars[1]);
    if (tid == 0) {
        asm volatile("mbarrier.init.shared.b64 [%0], %1;" :: "r"(bar0), "r"(1) : "memory");
        asm volatile("mbarrier.init.shared.b64 [%0], %1;" :: "r"(bar1), "r"(1) : "memory");
        // arm phase 0 of both barriers: arrive(1) + expect 1024 tx bytes
        asm volatile("mbarrier.arrive.expect_tx.shared.b64 _, [%0], %1;"
                     :: "r"(bar0), "r"(1024) : "memory");
        asm volatile("mbarrier.arrive.expect_tx.shared.b64 _, [%0], %1;"
                     :: "r"(bar1), "r"(1024) : "memory");
    }
    __syncthreads();
    asm volatile("barrier.cluster.arrive.aligned;" ::: "memory");
    asm volatile("barrier.cluster.wait.aligned;"  ::: "memory");

    int ph0 = 0, ph1 = 0;

    for (int it = 0; it < T_LEN; it++) {
        const int buf = it & 1;
        const int t = dir ? (T_LEN - 1 - it) : it;

        if (it > 0) {
            uint32_t ba = buf ? bar1 : bar0;
            int      ph = buf ? ph1  : ph0;
            asm volatile(
                "{\n\t.reg .pred P;\n\t"
                "BW_%=:\n\t"
                "mbarrier.try_wait.parity.acquire.cta.shared::cta.b64 P, [%0], %1, 0x989680;\n\t"
                "@P bra.uni BWD_%=;\n\t"
                "bra.uni BW_%=;\n\t"
                "BWD_%=:\n\t}"
                :: "r"(ba), "r"(ph) : "memory");
            if (buf) ph1 ^= 1; else ph0 ^= 1;
            // re-arm this barrier for its next phase (tid0 only; ordered
            // before this CTA's end-of-step signal by the __syncthreads below)
            if (tid == 0)
                asm volatile("mbarrier.arrive.expect_tx.shared.b64 _, [%0], %1;"
                             :: "r"(ba), "r"(1024) : "memory");
        }

        // prefetch pre-activation (leaders only)
        float gp = 0.f;
        if (seg == 0) gp = g_pre[dir][t][grow];

        // h . w on packed f32x2
        const ulonglong2* hp2 = (const ulonglong2*)(hbuf[buf] + seg * 64);
        uint64_t acc0 = 0, acc1 = 0;   // bit pattern of (0.f, 0.f)
        #pragma unroll
        for (int i = 0; i < 16; i++) {
            ulonglong2 hv = hp2[i];
            fma2(acc0, w2[2*i],     hv.x);
            fma2(acc1, w2[2*i + 1], hv.y);
        }
        float acc = unpack_sum(acc0) + unpack_sum(acc1);
        acc += __shfl_down_sync(0xffffffffu, acc, 2, 4);
        acc += __shfl_down_sync(0xffffffffu, acc, 1, 4);
        if (seg == 0) gates[lr] = acc + gp;
        __syncthreads();

        if (tid < 32) {
            float iv = gates[tid];
            float fv = gates[32 + tid];
            float gv = gates[64 + tid];
            float ov = gates[96 + tid];
            creg = fast_sig(fv) * creg + fast_sig(iv) * fast_tanh(gv);
            float h = fast_sig(ov) * fast_tanh(creg);

            const int hidx = (int)rank * 32 + tid;

            if (it < T_LEN - 1) {
                const int nbuf = buf ^ 1;
                uint32_t loc    = smem_u32(&hbuf[nbuf][hidx]);
                uint32_t barloc = nbuf ? bar1 : bar0;
                #pragma unroll
                for (int r = 0; r < 8; r++) {
                    asm volatile(
                        "{\n\t.reg .b32 ra, rb;\n\t"
                        "mapa.shared::cluster.u32 ra, %0, %2;\n\t"
                        "mapa.shared::cluster.u32 rb, %1, %2;\n\t"
                        "st.async.shared::cluster.mbarrier::complete_tx::bytes.b32 [ra], %3, [rb];\n\t}"
                        :: "r"(loc), "r"(barloc), "r"(r), "f"(h) : "memory");
                }
            }
            g_hs[dir][t][hidx] = h;
        }
    }
}

// ========================================================= Phase 3: feats
__global__ void feats_kernel(const float* __restrict__ Wlin,
                             const float* __restrict__ blin)
{
    __shared__ float Wl[C_TAGS][512];
    const int tid = threadIdx.x;
    for (int i = tid; i < C_TAGS * 512; i += 256)
        Wl[i >> 9][i & 511] = Wlin[i];
    __syncthreads();

    const int warp = tid >> 5, lane = tid & 31;
    const int t = blockIdx.x * 8 + warp;

    float hv[16];
    #pragma unroll
    for (int i = 0; i < 8; i++) hv[i]     = g_hs[0][t][lane + 32 * i];
    #pragma unroll
    for (int i = 0; i < 8; i++) hv[8 + i] = g_hs[1][t][lane + 32 * i];

    #pragma unroll
    for (int c = 0; c < C_TAGS; c++) {
        float a = 0.f;
        #pragma unroll
        for (int i = 0; i < 16; i++)
            a += hv[i] * Wl[c][lane + 32 * i];
        #pragma unroll
        for (int o = 16; o; o >>= 1)
            a += __shfl_down_sync(0xffffffffu, a, o);
        if (lane == 0) g_feats[t][c] = a + blin[c];
    }
}

// ================================================ Phase 4: Viterbi + trace
__global__ void viterbi_kernel(const float* __restrict__ trans,
                               float* __restrict__ out, int out_size)
{
    __shared__ uint8_t bps[T_LEN][C_TAGS];   // 24 KB
    __shared__ float   fvs[16];

    const int lane = threadIdx.x;
    float tr[C_TAGS];
    if (lane < C_TAGS) {
        #pragma unroll
        for (int p = 0; p < C_TAGS; p++) tr[p] = trans[lane * C_TAGS + p];
    }
    float fv = (lane == START_TAG) ? 0.f : NEGV;

    auto featload = [&](int idx) -> float {
        return (lane < C_TAGS && idx < T_LEN) ? g_feats[idx][lane] : 0.f;
    };
    auto vstep = [&](int t, float ft) {
        if (lane < C_TAGS) fvs[lane] = fv;
        __syncwarp();
        if (lane < C_TAGS) {
            float s[C_TAGS];
            #pragma unroll
            for (int p = 0; p < C_TAGS; p++) s[p] = fvs[p] + tr[p];
            // FMNMX tree (depth 4) instead of serial predicated-select chain
            float m01 = fmaxf(s[0], s[1]),  m23  = fmaxf(s[2], s[3]);
            float m45 = fmaxf(s[4], s[5]),  m67  = fmaxf(s[6], s[7]);
            float m89 = fmaxf(s[8], s[9]),  mab  = fmaxf(s[10], s[11]);
            float q0 = fmaxf(m01, m23), q1 = fmaxf(m45, m67), q2 = fmaxf(m89, mab);
            float best = fmaxf(fmaxf(q0, q1), q2);
            unsigned mask = 0;
            #pragma unroll
            for (int p = 0; p < C_TAGS; p++)
                mask |= (s[p] == best) ? (1u << p) : 0u;
            bps[t][lane] = (uint8_t)(__ffs(mask) - 1);   // first argmax
            fv = best + ft;
        }
        __syncwarp();
    };

    float f0 = featload(0), f1 = featload(1), f2 = featload(2), f3 = featload(3);
    for (int t = 0; t < T_LEN; t += 4) {
        float n0 = featload(t + 4), n1 = featload(t + 5);
        float n2 = featload(t + 6), n3 = featload(t + 7);
        vstep(t + 0, f0);
        vstep(t + 1, f1);
        vstep(t + 2, f2);
        vstep(t + 3, f3);
        f0 = n0; f1 = n1; f2 = n2; f3 = n3;
    }

    if (lane < C_TAGS) fvs[lane] = fv + trans[STOP_TAG * C_TAGS + lane];
    __syncwarp();

    if (lane == 0) {
        float best = fvs[0]; int bt = 0;
        #pragma unroll
        for (int p = 1; p < C_TAGS; p++)
            if (fvs[p] > best) { best = fvs[p]; bt = p; }

        if (out_size >= 1) out[0] = best;
        if (out_size >= T_LEN + 1) {
            int tag = bt;
            for (int t = T_LEN - 1; t >= 1; t--) {
                out[1 + t] = (float)tag;
                tag = bps[t][tag];
            }
            out[1] = (float)tag;
        }
    }
}

// ================================================================= launch
extern "C" void kernel_launch(void* const* d_in, const int* in_sizes, int n_in,
                              void* d_out, int out_size)
{
    const int*   sent   = (const int*)  d_in[0];
    const float* emb    = (const float*)d_in[1];
    const float* Wih_f  = (const float*)d_in[2];
    const float* Whh_f  = (const float*)d_in[3];
    const float* bih_f  = (const float*)d_in[4];
    const float* bhh_f  = (const float*)d_in[5];
    const float* Wih_b  = (const float*)d_in[6];
    const float* Whh_b  = (const float*)d_in[7];
    const float* bih_b  = (const float*)d_in[8];
    const float* bhh_b  = (const float*)d_in[9];
    const float* Wlin   = (const float*)d_in[10];
    const float* blin   = (const float*)d_in[11];
    const float* h0     = (const float*)d_in[12];
    const float* c0     = (const float*)d_in[13];
    const float* transi = (const float*)d_in[14];
    float* out = (float*)d_out;

    gates_gemm<<<dim3(T_LEN / 32, G4 / 32, 2), 256>>>(
        sent, emb, Wih_f, bih_f, bhh_f, Wih_b, bih_b, bhh_b);

    lstm_rec<<<16, 512>>>(Whh_f, Whh_b, h0, c0);

    feats_kernel<<<T_LEN / 8, 256>>>(Wlin, blin);

    viterbi_kernel<<<1, 32>>>(transi, out, out_size);
}